// round 13
// baseline (speedup 1.0000x reference)
#include <cuda_runtime.h>
#include <cuda_fp16.h>
#include <cstdint>

// Problem constants (fixed by the dataset)
#define N_SRC   50000
#define N_EDGES 150000
#define D       512
#define NBLK_N  196          // ceil(N_SRC / 256)
#define NBLK_E  587          // ceil(N_EDGES / 256)

// ---------------------------------------------------------------------------
// Device scratch (no allocations allowed)
// ---------------------------------------------------------------------------
__device__ __half g_Wh[(size_t)D * D];         // W rounded to fp16
__device__ int    g_count[N_SRC];
__device__ int    g_offset[N_SRC + 1];
__device__ int    g_cursor[N_SRC];
__device__ int    g_bsum[256];
__device__ int    g_sorted_src[N_EDGES];

__device__ __forceinline__ void mma_f16_16x8x16(
    float d[4], const unsigned a[4], const unsigned b[2], const float c[4])
{
    asm volatile(
        "mma.sync.aligned.m16n8k16.row.col.f32.f16.f16.f32 "
        "{%0,%1,%2,%3}, {%4,%5,%6,%7}, {%8,%9}, {%10,%11,%12,%13};"
        : "=f"(d[0]), "=f"(d[1]), "=f"(d[2]), "=f"(d[3])
        : "r"(a[0]), "r"(a[1]), "r"(a[2]), "r"(a[3]),
          "r"(b[0]), "r"(b[1]),
          "f"(c[0]), "f"(c[1]), "f"(c[2]), "f"(c[3]));
}

__device__ __forceinline__ void ldsm_x4(unsigned r[4], unsigned addr) {
    asm volatile("ldmatrix.sync.aligned.m8n8.x4.shared.b16 {%0,%1,%2,%3}, [%4];"
                 : "=r"(r[0]), "=r"(r[1]), "=r"(r[2]), "=r"(r[3]) : "r"(addr));
}

// ---------------------------------------------------------------------------
// CSR construction (unchanged, proven path)
// ---------------------------------------------------------------------------
__global__ void zero_count_kernel() {
    int i = blockIdx.x * 256 + threadIdx.x;
    if (i < N_SRC) g_count[i] = 0;
    if (i == 0)    g_offset[N_SRC] = N_EDGES;
}

__global__ void hist_kernel(const int* __restrict__ dst_idx,
                            const float* __restrict__ W) {
    int e = blockIdx.x * 256 + threadIdx.x;
    if (e < N_EDGES) atomicAdd(&g_count[dst_idx[e]], 1);
    if (e < (D * D) / 4) {
        float4 v = reinterpret_cast<const float4*>(W)[e];
        __half2 h0 = __floats2half2_rn(v.x, v.y);
        __half2 h1 = __floats2half2_rn(v.z, v.w);
        uint2 u;
        u.x = *reinterpret_cast<unsigned*>(&h0);
        u.y = *reinterpret_cast<unsigned*>(&h1);
        reinterpret_cast<uint2*>(g_Wh)[e] = u;
    }
}

__global__ void scan1_kernel() {
    __shared__ int sh[256];
    int t = threadIdx.x;
    int idx = blockIdx.x * 256 + t;
    int v = (idx < N_SRC) ? g_count[idx] : 0;
    sh[t] = v; __syncthreads();
    #pragma unroll
    for (int off = 1; off < 256; off <<= 1) {
        int x = (t >= off) ? sh[t - off] : 0;
        __syncthreads();
        sh[t] += x;
        __syncthreads();
    }
    if (idx < N_SRC) g_offset[idx] = sh[t] - v;
    if (t == 255)    g_bsum[blockIdx.x] = sh[255];
}

__global__ void scan3_kernel() {
    __shared__ int s_base;
    int t = threadIdx.x;
    if (t == 0) s_base = 0;
    __syncthreads();
    int partial = 0;
    for (int j = t; j < blockIdx.x; j += 256) partial += g_bsum[j];
    if (partial) atomicAdd(&s_base, partial);
    __syncthreads();
    int i = blockIdx.x * 256 + t;
    if (i < N_SRC) {
        int o = g_offset[i] + s_base;
        g_offset[i] = o;
        g_cursor[i] = o;
    }
}

__global__ void fill_kernel(const int* __restrict__ src_idx,
                            const int* __restrict__ dst_idx) {
    int e = blockIdx.x * 256 + threadIdx.x;
    if (e < N_EDGES) {
        int pos = atomicAdd(&g_cursor[dst_idx[e]], 1);
        g_sorted_src[pos] = src_idx[e];
    }
}

// ---------------------------------------------------------------------------
// Fused gather-GEMM: out = (segment_sum(src_h)) @ W^T + b.
// BM=64, BN=512 (full width -> each dst row gathered by exactly one CTA),
// BK=32; 512 threads (16 warps, warp tile 64x32, acc=64 regs).
// A tile built in-kernel: per row-chunk, sum f32 edges in regs -> fp16 -> STS,
// double-buffered; gather for tile ks+1 issued before mma of tile ks (latency
// hidden under ~2000 cyc of HMMA). B (=W fp16) double-buffered via cp.async.
// Numerics identical to the former standalone aggregate kernel.
// smem halves layout: A0[0,2560) A1[2560,5120) B0[5120,25600) B1[25600,46080)
// LDT=40 halves (80B row): 16B-aligned chunks; ldmatrix row step 80B -> 8
// phase addresses hit distinct 16B lanes (80*r mod 128 is a permutation).
// ---------------------------------------------------------------------------
#define BM 64
#define BK 32
#define LDT 40
#define A_HALVES (BM * LDT)                 // 2560
#define B_HALVES (D * LDT)                  // 20480
#define SMEM_HALVES (2 * A_HALVES + 2 * B_HALVES)   // 46080
#define GEMM_SMEM_BYTES (SMEM_HALVES * 2)           // 92160

__global__ void __launch_bounds__(512, 1) fused_gemm_kernel(
    const float* __restrict__ src_h,
    const float* __restrict__ bias,
    float*       __restrict__ out)
{
    extern __shared__ __half smem[];
    uint32_t smem_b;
    {
        uint64_t tmp = __cvta_generic_to_shared(smem);
        smem_b = (uint32_t)tmp;
    }

    const int tid  = threadIdx.x;
    const int warp = tid >> 5;
    const int lane = tid & 31;
    const int g    = lane >> 2;   // 0..7
    const int t    = lane & 3;    // 0..3

    const int wn = warp * 32;           // 16 warps tile N=512
    const int bm = blockIdx.x * BM;

    // Gather role: 8 threads per A row, 4 f32 (one float4) each
    const int grow_l = tid >> 3;        // 0..63
    const int sub    = tid & 7;         // 0..7 -> f32 offset sub*4
    const int grow   = bm + grow_l;
    int estart = 0, eend = 0;
    if (grow < N_SRC) {
        estart = g_offset[grow];
        eend   = g_offset[grow + 1];
    }

    // B cp.async role: 4 rows x 16B per thread per stage
    const int brow   = tid >> 2;        // 0..127
    const int bchunk = (tid & 3) * 8;   // half offset: 0,8,16,24

    // ldmatrix lane address components
    const int ar = lane & 15;
    const int ak = (lane >> 4) * 8;
    const int br = ((lane >> 4) << 3) + (lane & 7);
    const int bk = ((lane >> 3) & 1) * 8;

    auto load_B = [&](int s, int k0) {
        uint32_t Bs = smem_b + (2 * A_HALVES + s * B_HALVES) * 2;
        #pragma unroll
        for (int i = 0; i < 4; i++) {
            int row = brow + i * 128;
            const __half* gb = g_Wh + (size_t)row * D + k0 + bchunk;
            uint32_t db = Bs + (row * LDT + bchunk) * 2;
            asm volatile("cp.async.cg.shared.global [%0], [%1], 16;"
                         :: "r"(db), "l"(gb));
        }
        asm volatile("cp.async.commit_group;");
    };

    auto gather_A = [&](int k0, float4& a) {
        a = make_float4(0.f, 0.f, 0.f, 0.f);
        for (int j = estart; j < eend; j++) {
            int s = g_sorted_src[j];
            float4 v = *reinterpret_cast<const float4*>(
                           src_h + (size_t)s * D + k0 + sub * 4);
            a.x += v.x; a.y += v.y; a.z += v.z; a.w += v.w;
        }
    };

    auto store_A = [&](int s, const float4& a) {
        __half2 h0 = __floats2half2_rn(a.x, a.y);
        __half2 h1 = __floats2half2_rn(a.z, a.w);
        uint2 u;
        u.x = *reinterpret_cast<const unsigned*>(&h0);
        u.y = *reinterpret_cast<const unsigned*>(&h1);
        *reinterpret_cast<uint2*>(
            smem + s * A_HALVES + grow_l * LDT + sub * 4) = u;
    };

    float acc[4][4][4];
    #pragma unroll
    for (int mt = 0; mt < 4; mt++)
        #pragma unroll
        for (int nt = 0; nt < 4; nt++)
            #pragma unroll
            for (int r = 0; r < 4; r++)
                acc[mt][nt][r] = 0.f;

    // Prologue: B0, B1 in flight; A0 gathered + stored
    load_B(0, 0);
    load_B(1, BK);
    {
        float4 a0;
        gather_A(0, a0);
        store_A(0, a0);
    }

    const int NK = D / BK;   // 16
    for (int ks = 0; ks < NK; ks++) {
        const int buf = ks & 1;
        asm volatile("cp.async.wait_group 1;" ::: "memory");
        __syncthreads();   // B[buf] + A[buf] visible to all

        // Issue next tile's gather early; LDG latency hides under mma
        float4 anext;
        if (ks + 1 < NK) gather_A((ks + 1) * BK, anext);

        uint32_t As = smem_b + (buf * A_HALVES) * 2;
        uint32_t Bs = smem_b + (2 * A_HALVES + buf * B_HALVES) * 2;

        uint32_t aaddr[4], baddr[2];
        #pragma unroll
        for (int mt = 0; mt < 4; mt++)
            aaddr[mt] = As + ((mt * 16 + ar) * LDT + ak) * 2;
        #pragma unroll
        for (int np = 0; np < 2; np++)
            baddr[np] = Bs + ((wn + np * 16 + br) * LDT + bk) * 2;

        #pragma unroll
        for (int kk = 0; kk < BK; kk += 16) {   // 2 x K16 steps
            unsigned afr[4][4];
            unsigned bfr[4][2];
            #pragma unroll
            for (int mt = 0; mt < 4; mt++)
                ldsm_x4(afr[mt], aaddr[mt] + kk * 2);
            #pragma unroll
            for (int np = 0; np < 2; np++) {
                unsigned r[4];
                ldsm_x4(r, baddr[np] + kk * 2);
                bfr[np * 2    ][0] = r[0];
                bfr[np * 2    ][1] = r[1];
                bfr[np * 2 + 1][0] = r[2];
                bfr[np * 2 + 1][1] = r[3];
            }
            #pragma unroll
            for (int mt = 0; mt < 4; mt++)
                #pragma unroll
                for (int nt = 0; nt < 4; nt++)
                    mma_f16_16x8x16(acc[mt][nt], afr[mt], bfr[nt], acc[mt][nt]);
        }

        // Stage next A into the other buffer (current buf still being read
        // is fine: different buffer), then release this stage's B buffer.
        if (ks + 1 < NK) store_A(buf ^ 1, anext);
        __syncthreads();   // everyone done with B[buf] and A stores visible
        if (ks + 2 < NK) load_B(buf, (ks + 2) * BK);
    }

    // Epilogue: add bias, store
    #pragma unroll
    for (int mt = 0; mt < 4; mt++) {
        int row0 = bm + mt * 16 + g;
        int row1 = row0 + 8;
        #pragma unroll
        for (int nt = 0; nt < 4; nt++) {
            int col = wn + nt * 8 + 2 * t;
            float b0 = __ldg(bias + col);
            float b1 = __ldg(bias + col + 1);
            if (row0 < N_SRC) {
                out[(size_t)row0 * D + col    ] = acc[mt][nt][0] + b0;
                out[(size_t)row0 * D + col + 1] = acc[mt][nt][1] + b1;
            }
            if (row1 < N_SRC) {
                out[(size_t)row1 * D + col    ] = acc[mt][nt][2] + b0;
                out[(size_t)row1 * D + col + 1] = acc[mt][nt][3] + b1;
            }
        }
    }
}

// ---------------------------------------------------------------------------
// Launch. Inputs per metadata order:
//   0: src_h [50000,512] f32   1: W [512,512] f32   2: b [512] f32
//   3: src_idx [150000] i32    4: dst_idx [150000] i32   5: n_dst scalar
// ---------------------------------------------------------------------------
extern "C" void kernel_launch(void* const* d_in, const int* in_sizes, int n_in,
                              void* d_out, int out_size)
{
    const float* src_h   = (const float*)d_in[0];
    const float* W       = (const float*)d_in[1];
    const float* bias    = (const float*)d_in[2];
    const int*   src_idx = (const int*)d_in[3];
    const int*   dst_idx = (const int*)d_in[4];
    float*       out     = (float*)d_out;

    cudaFuncSetAttribute(fused_gemm_kernel,
                         cudaFuncAttributeMaxDynamicSharedMemorySize,
                         GEMM_SMEM_BYTES);

    zero_count_kernel<<<NBLK_N, 256>>>();
    hist_kernel<<<NBLK_E, 256>>>(dst_idx, W);
    scan1_kernel<<<NBLK_N, 256>>>();
    scan3_kernel<<<NBLK_N, 256>>>();
    fill_kernel<<<NBLK_E, 256>>>(src_idx, dst_idx);

    int grid = (N_SRC + BM - 1) / BM;   // 782
    fused_gemm_kernel<<<grid, 512, GEMM_SMEM_BYTES>>>(src_h, bias, out);
}

// round 14
// speedup vs baseline: 1.8055x; 1.8055x over previous
#include <cuda_runtime.h>
#include <cuda_fp16.h>
#include <cstdint>

// Problem constants (fixed by the dataset)
#define N_SRC   50000
#define N_EDGES 150000
#define D       512
#define NBLK_N  196          // ceil(N_SRC / 256)
#define NBLK_E  587          // ceil(N_EDGES / 256)

// ---------------------------------------------------------------------------
// Device scratch (no allocations allowed)
// ---------------------------------------------------------------------------
__device__ __half g_aggh[(size_t)N_SRC * D];   // aggregated messages (fp16)
__device__ __half g_Wh[(size_t)D * D];         // W rounded to fp16
__device__ int    g_count[N_SRC];
__device__ int    g_offset[N_SRC + 1];
__device__ int    g_cursor[N_SRC];
__device__ int    g_bsum[256];
__device__ int    g_sorted_src[N_EDGES];

__device__ __forceinline__ void mma_f16_16x8x16(
    float d[4], const unsigned a[4], const unsigned b[2], const float c[4])
{
    asm volatile(
        "mma.sync.aligned.m16n8k16.row.col.f32.f16.f16.f32 "
        "{%0,%1,%2,%3}, {%4,%5,%6,%7}, {%8,%9}, {%10,%11,%12,%13};"
        : "=f"(d[0]), "=f"(d[1]), "=f"(d[2]), "=f"(d[3])
        : "r"(a[0]), "r"(a[1]), "r"(a[2]), "r"(a[3]),
          "r"(b[0]), "r"(b[1]),
          "f"(c[0]), "f"(c[1]), "f"(c[2]), "f"(c[3]));
}

__device__ __forceinline__ void ldsm_x4(unsigned r[4], unsigned addr) {
    asm volatile("ldmatrix.sync.aligned.m8n8.x4.shared.b16 {%0,%1,%2,%3}, [%4];"
                 : "=r"(r[0]), "=r"(r[1]), "=r"(r[2]), "=r"(r[3]) : "r"(addr));
}

// ---------------------------------------------------------------------------
// CSR construction (counts zeroed by cudaMemsetAsync in kernel_launch)
// ---------------------------------------------------------------------------

// Histogram + (independent) W->fp16 conversion folded together
__global__ void hist_kernel(const int* __restrict__ dst_idx,
                            const float* __restrict__ W) {
    int e = blockIdx.x * 256 + threadIdx.x;
    if (e == 0) g_offset[N_SRC] = N_EDGES;
    if (e < N_EDGES) atomicAdd(&g_count[dst_idx[e]], 1);
    // W: 65536 float4s over 150272 threads
    if (e < (D * D) / 4) {
        float4 v = reinterpret_cast<const float4*>(W)[e];
        __half2 h0 = __floats2half2_rn(v.x, v.y);
        __half2 h1 = __floats2half2_rn(v.z, v.w);
        uint2 u;
        u.x = *reinterpret_cast<unsigned*>(&h0);
        u.y = *reinterpret_cast<unsigned*>(&h1);
        reinterpret_cast<uint2*>(g_Wh)[e] = u;
    }
}

__global__ void scan1_kernel() {
    __shared__ int sh[256];
    int t = threadIdx.x;
    int idx = blockIdx.x * 256 + t;
    int v = (idx < N_SRC) ? g_count[idx] : 0;
    sh[t] = v; __syncthreads();
    #pragma unroll
    for (int off = 1; off < 256; off <<= 1) {
        int x = (t >= off) ? sh[t - off] : 0;
        __syncthreads();
        sh[t] += x;
        __syncthreads();
    }
    if (idx < N_SRC) g_offset[idx] = sh[t] - v;
    if (t == 255)    g_bsum[blockIdx.x] = sh[255];
}

// scan3 with integrated block-sum prefix
__global__ void scan3_kernel() {
    __shared__ int s_base;
    int t = threadIdx.x;
    if (t == 0) s_base = 0;
    __syncthreads();
    int partial = 0;
    for (int j = t; j < blockIdx.x; j += 256) partial += g_bsum[j];
    if (partial) atomicAdd(&s_base, partial);
    __syncthreads();
    int i = blockIdx.x * 256 + t;
    if (i < N_SRC) {
        int o = g_offset[i] + s_base;
        g_offset[i] = o;
        g_cursor[i] = o;
    }
}

__global__ void fill_kernel(const int* __restrict__ src_idx,
                            const int* __restrict__ dst_idx) {
    int e = blockIdx.x * 256 + threadIdx.x;
    if (e < N_EDGES) {
        int pos = atomicAdd(&g_cursor[dst_idx[e]], 1);
        g_sorted_src[pos] = src_idx[e];
    }
}

// ---------------------------------------------------------------------------
// Gather-aggregate: one block (128 threads) per dst node. Gathers f32 rows
// (src stays L2-hot across ~3x reuse), fp32 accumulate, fp16 write.
// ---------------------------------------------------------------------------
__global__ void __launch_bounds__(128) aggregate_kernel(
    const float* __restrict__ src_h)
{
    int d = blockIdx.x;
    int t = threadIdx.x;                 // 0..127 -> one float4 each
    int start = g_offset[d];
    int end   = g_offset[d + 1];
    float4 acc = make_float4(0.f, 0.f, 0.f, 0.f);
    for (int j = start; j < end; j++) {
        int s = g_sorted_src[j];
        float4 v = reinterpret_cast<const float4*>(src_h + (size_t)s * D)[t];
        acc.x += v.x; acc.y += v.y; acc.z += v.z; acc.w += v.w;
    }
    __half2 h0 = __floats2half2_rn(acc.x, acc.y);
    __half2 h1 = __floats2half2_rn(acc.z, acc.w);
    uint2 u;
    u.x = *reinterpret_cast<unsigned*>(&h0);
    u.y = *reinterpret_cast<unsigned*>(&h1);
    reinterpret_cast<uint2*>(g_aggh + (size_t)d * D)[t] = u;
}

// ---------------------------------------------------------------------------
// GEMM: out = agg @ W^T + b, FP16 mma.m16n8k16 (f32 accum).
// BM=128, BN=128, BK=64 halves; 256 threads, 8 warps (4M x 2N), warp 32x64.
// 2 CTAs/SM, 3-stage cp.async pipeline (wait_group 1), ldmatrix fragments.
// At the legacy-HMMA rate ceiling (~512 MAC/cyc/SM) -> left unchanged.
// ---------------------------------------------------------------------------
#define BM 128
#define BN 128
#define BK 64
#define LDT 72
#define A_BYTES (BM * LDT * 2)              // 18432
#define STAGE_BYTES (2 * A_BYTES)           // A + B = 36864
#define NSTAGE 3
#define GEMM_SMEM_BYTES (NSTAGE * STAGE_BYTES)   // 110592

__global__ void __launch_bounds__(256, 2) gemm_kernel(
    const float* __restrict__ bias,
    float*       __restrict__ out)
{
    extern __shared__ __half smem[];
    uint32_t smem_b;
    {
        uint64_t tmp = __cvta_generic_to_shared(smem);
        smem_b = (uint32_t)tmp;
    }

    const int tid  = threadIdx.x;
    const int warp = tid >> 5;
    const int lane = tid & 31;
    const int g    = lane >> 2;   // 0..7
    const int t    = lane & 3;    // 0..3

    const int wm = (warp & 3) * 32;    // 4 warps along M
    const int wn = (warp >> 2) * 64;   // 2 warps along N

    const int bm = blockIdx.y * BM;
    const int bn = blockIdx.x * BN;

    // ldmatrix per-lane address components (half-element offsets)
    const int ar = lane & 15;                         // A row within 16
    const int ak = (lane >> 4) * 8;                   // A k-offset (0/8)
    const int br = ((lane >> 4) << 3) + (lane & 7);   // B row within 16
    const int bk = ((lane >> 3) & 1) * 8;             // B k-offset (0/8)

    // Tile-load indexing: 16B chunk = 8 halves; 8 chunks per row (BK=64).
    const int chunk = (tid & 7) * 8;      // half offset in row
    const int rowb  = tid >> 3;           // 0..31

    float acc[2][8][4];
    #pragma unroll
    for (int mt = 0; mt < 2; mt++)
        #pragma unroll
        for (int nt = 0; nt < 8; nt++)
            #pragma unroll
            for (int r = 0; r < 4; r++)
                acc[mt][nt][r] = 0.f;

    auto load_tiles = [&](int s, int k0) {
        uint32_t As = smem_b + s * STAGE_BYTES;
        uint32_t Bs = As + A_BYTES;
        // A: 128 rows -> 4 passes of 32 rows
        #pragma unroll
        for (int i = 0; i < 4; i++) {
            int row  = rowb + i * 32;
            int arow = bm + row;
            const __half* ga = g_aggh + (size_t)arow * D + k0 + chunk;
            uint32_t da = As + (row * LDT + chunk) * 2;
            int sz = (arow < N_SRC) ? 16 : 0;   // zero-fill OOB rows
            asm volatile("cp.async.cg.shared.global [%0], [%1], 16, %2;"
                         :: "r"(da), "l"(ga), "r"(sz));
        }
        // B: 128 rows (always in-bounds: bn+row < 512)
        #pragma unroll
        for (int i = 0; i < 4; i++) {
            int row = rowb + i * 32;
            const __half* gb = g_Wh + (size_t)(bn + row) * D + k0 + chunk;
            uint32_t db = Bs + (row * LDT + chunk) * 2;
            asm volatile("cp.async.cg.shared.global [%0], [%1], 16;"
                         :: "r"(db), "l"(gb));
        }
        asm volatile("cp.async.commit_group;");
    };

    const int NK = D / BK;   // 8
    load_tiles(0, 0);
    load_tiles(1, BK);

    int buf = 0;
    for (int ks = 0; ks < NK; ks++) {
        asm volatile("cp.async.wait_group 1;" ::: "memory");
        __syncthreads();
        if (ks + 2 < NK) {
            int nb = buf + 2; if (nb >= NSTAGE) nb -= NSTAGE;
            load_tiles(nb, (ks + 2) * BK);
        }

        uint32_t As = smem_b + buf * STAGE_BYTES;
        uint32_t Bs = As + A_BYTES;

        // per-lane ldmatrix base addresses (bytes)
        uint32_t aaddr[2], baddr[4];
        #pragma unroll
        for (int mt = 0; mt < 2; mt++)
            aaddr[mt] = As + ((wm + mt * 16 + ar) * LDT + ak) * 2;
        #pragma unroll
        for (int np = 0; np < 4; np++)
            baddr[np] = Bs + ((wn + np * 16 + br) * LDT + bk) * 2;

        #pragma unroll
        for (int kk = 0; kk < BK; kk += 16) {   // 4 x K16 steps
            unsigned afr[2][4];
            unsigned bfr[8][2];
            #pragma unroll
            for (int mt = 0; mt < 2; mt++)
                ldsm_x4(afr[mt], aaddr[mt] + kk * 2);
            #pragma unroll
            for (int np = 0; np < 4; np++) {
                unsigned r[4];
                ldsm_x4(r, baddr[np] + kk * 2);
                bfr[np * 2    ][0] = r[0];
                bfr[np * 2    ][1] = r[1];
                bfr[np * 2 + 1][0] = r[2];
                bfr[np * 2 + 1][1] = r[3];
            }
            #pragma unroll
            for (int mt = 0; mt < 2; mt++)
                #pragma unroll
                for (int nt = 0; nt < 8; nt++)
                    mma_f16_16x8x16(acc[mt][nt], afr[mt], bfr[nt], acc[mt][nt]);
        }
        if (++buf >= NSTAGE) buf = 0;
    }

    // Epilogue: add bias, store
    #pragma unroll
    for (int mt = 0; mt < 2; mt++) {
        int row0 = bm + wm + mt * 16 + g;
        int row1 = row0 + 8;
        #pragma unroll
        for (int nt = 0; nt < 8; nt++) {
            int col = bn + wn + nt * 8 + 2 * t;
            float b0 = __ldg(bias + col);
            float b1 = __ldg(bias + col + 1);
            if (row0 < N_SRC) {
                out[(size_t)row0 * D + col    ] = acc[mt][nt][0] + b0;
                out[(size_t)row0 * D + col + 1] = acc[mt][nt][1] + b1;
            }
            if (row1 < N_SRC) {
                out[(size_t)row1 * D + col    ] = acc[mt][nt][2] + b0;
                out[(size_t)row1 * D + col + 1] = acc[mt][nt][3] + b1;
            }
        }
    }
}

// ---------------------------------------------------------------------------
// Launch. Inputs per metadata order:
//   0: src_h [50000,512] f32   1: W [512,512] f32   2: b [512] f32
//   3: src_idx [150000] i32    4: dst_idx [150000] i32   5: n_dst scalar
// ---------------------------------------------------------------------------
extern "C" void kernel_launch(void* const* d_in, const int* in_sizes, int n_in,
                              void* d_out, int out_size)
{
    const float* src_h   = (const float*)d_in[0];
    const float* W       = (const float*)d_in[1];
    const float* bias    = (const float*)d_in[2];
    const int*   src_idx = (const int*)d_in[3];
    const int*   dst_idx = (const int*)d_in[4];
    float*       out     = (float*)d_out;

    cudaFuncSetAttribute(gemm_kernel,
                         cudaFuncAttributeMaxDynamicSharedMemorySize,
                         GEMM_SMEM_BYTES);

    // Zero edge counts via async memset (graph-capturable, no alloc)
    void* count_ptr = nullptr;
    cudaGetSymbolAddress(&count_ptr, g_count);
    cudaMemsetAsync(count_ptr, 0, N_SRC * sizeof(int));

    hist_kernel<<<NBLK_E, 256>>>(dst_idx, W);
    scan1_kernel<<<NBLK_N, 256>>>();
    scan3_kernel<<<NBLK_N, 256>>>();
    fill_kernel<<<NBLK_E, 256>>>(src_idx, dst_idx);
    aggregate_kernel<<<N_SRC, 128>>>(src_h);

    dim3 grid(D / BN, (N_SRC + BM - 1) / BM);   // (4, 391)
    gemm_kernel<<<grid, 256, GEMM_SMEM_BYTES>>>(bias, out);
}